// round 3
// baseline (speedup 1.0000x reference)
#include <cuda_runtime.h>
#include <cuda_bf16.h>
#include <cstdint>

// ---------------------------------------------------------------------------
// MeshRefineNet on GB300 (sm_103a), R3: mma.sync (HMMA) split-bf16 GEMMs.
// (tcgen05 PTX is rejected by this harness's compute_103 PTX stage.)
//   layer i: h0 = x@W0+b0; h1 = x@W1+b1; out = h0 + scatter_add(h1 over edges)
//   relu after layers 0..2; skip (x += features) before layer 3; layer 3 dout=3.
// GEMM per tile: D[128,256] = A[128,128] @ [W0|W1] via
//   Ahi@Whi + Ahi@Wlo + Alo@Whi   (bf16 mma.sync, fp32 accum, rel err ~1e-5)
// ---------------------------------------------------------------------------

#define NMAX 320000

__device__ float g_bufA[NMAX * 128];
__device__ float g_bufB[NMAX * 128];
__device__ float g_h1 [NMAX * 128];
__device__ float g_h1s[NMAX * 3];

// pre-split weight images, linear Bt[n][k] row-major (built once per launch)
__device__ __align__(16) __nv_bfloat16 g_Whi[3][256 * 128];
__device__ __align__(16) __nv_bfloat16 g_Wlo[3][256 * 128];
__device__ float g_bias[3][256];

// ======================= helpers ===========================================
__device__ __forceinline__ uint32_t smem_to_u32(const void* p) {
    uint32_t a;
    asm("{ .reg .u64 t; cvta.to.shared.u64 t, %1; cvt.u32.u64 %0, t; }"
        : "=r"(a) : "l"(p));
    return a;
}
__device__ __forceinline__ uint32_t pkbf(float a, float b) {
    __nv_bfloat162 t = __floats2bfloat162_rn(a, b);
    return *(uint32_t*)&t;
}
// XOR-swizzled offset for bf16 tile images with 256B rows (128 halves).
// row-local 16B block index kblk in [0,16); swizzle low 3 bits by row.
__device__ __forceinline__ uint32_t aswz(uint32_t row, uint32_t kblk) {
    return row * 256u + ((((kblk ^ row) & 7u) | (kblk & 8u)) << 4);
}
__device__ __forceinline__ void ldsm_x4(uint32_t& r0, uint32_t& r1,
                                        uint32_t& r2, uint32_t& r3, uint32_t addr) {
    asm volatile("ldmatrix.sync.aligned.m8n8.x4.shared.b16 {%0,%1,%2,%3}, [%4];"
                 : "=r"(r0), "=r"(r1), "=r"(r2), "=r"(r3) : "r"(addr));
}
__device__ __forceinline__ void mma16816(float* d, const uint32_t* a,
                                         const uint32_t* b) {
    asm volatile("mma.sync.aligned.m16n8k16.row.col.f32.bf16.bf16.f32 "
                 "{%0,%1,%2,%3}, {%4,%5,%6,%7}, {%8,%9}, {%0,%1,%2,%3};"
                 : "+f"(d[0]), "+f"(d[1]), "+f"(d[2]), "+f"(d[3])
                 : "r"(a[0]), "r"(a[1]), "r"(a[2]), "r"(a[3]),
                   "r"(b[0]), "r"(b[1]));
}

// ======================= weight prep (once per launch) =====================
// Bt[n][k] = W[k][n] (n<128 from W0, else W1), split into hi/lo bf16, linear.
__global__ void prep_w_kernel(const float* __restrict__ W0, const float* __restrict__ b0,
                              const float* __restrict__ W1, const float* __restrict__ b1,
                              __nv_bfloat16* __restrict__ hi, __nv_bfloat16* __restrict__ lo,
                              float* __restrict__ biasOut)
{
    int t0 = blockIdx.x * blockDim.x + threadIdx.x;
    if (t0 < 256) biasOut[t0] = (t0 < 128) ? b0[t0] : b1[t0 - 128];
    uint32_t* hip = (uint32_t*)hi;
    uint32_t* lop = (uint32_t*)lo;
    for (int idx = t0; idx < 256 * 64; idx += blockDim.x * gridDim.x) {
        int n = idx >> 6, p = idx & 63;
        int k = p * 2;
        float x0, x1;
        if (n < 128) { x0 = W0[k * 128 + n]; x1 = W0[(k + 1) * 128 + n]; }
        else         { x0 = W1[k * 128 + n - 128]; x1 = W1[(k + 1) * 128 + n - 128]; }
        float h0f = __bfloat162float(__float2bfloat16_rn(x0));
        float h1f = __bfloat162float(__float2bfloat16_rn(x1));
        hip[idx] = pkbf(x0, x1);
        lop[idx] = pkbf(x0 - h0f, x1 - h1f);
    }
}

// ======================= HMMA dual-GEMM ====================================
// smem: A_hi | A_lo | B_hi | B_lo, all in swizzled 256B-row bf16 layout.
static constexpr int SM_A_HI = 0;
static constexpr int SM_A_LO = 32768;
static constexpr int SM_B_HI = 65536;
static constexpr int SM_B_LO = 131072;
static constexpr int SM_DYN  = 196608;

template<int MODE>   // 0 = raw input, 1 = relu(input)
__global__ __launch_bounds__(512, 1)
void gemm_mma_kernel(const float* __restrict__ in,
                     const __nv_bfloat16* __restrict__ Whi,
                     const __nv_bfloat16* __restrict__ Wlo,
                     const float* __restrict__ bias256,
                     float* __restrict__ agg, float* __restrict__ h1v, int n)
{
    extern __shared__ char sm[];
    const uint32_t sbase = smem_to_u32(sm);
    const int tid  = threadIdx.x;
    const int wid  = tid >> 5;
    const int lane = tid & 31;
    const int m0   = blockIdx.x * 128;

    // ---- stage B (hi+lo): 256 rows x 64 u32-pairs each, swizzled store ----
    {
        const uint32_t* srcH = (const uint32_t*)Whi;
        const uint32_t* srcL = (const uint32_t*)Wlo;
#pragma unroll
        for (int u = 0; u < 32; u++) {
            int idx = u * 512 + tid;            // 0..16383
            int row = idx >> 6, p = idx & 63;
            uint32_t off = aswz(row, p >> 2) + (p & 3) * 4;
            *(uint32_t*)(sm + SM_B_HI + off) = srcH[idx];
            *(uint32_t*)(sm + SM_B_LO + off) = srcL[idx];
        }
    }

    // ---- stage A (hi/lo split, optional relu), swizzled store -------------
    {
#pragma unroll
        for (int u = 0; u < 16; u++) {
            int idx = u * 512 + tid;            // 0..8191
            int row = idx >> 6, p = idx & 63;
            int gr = m0 + row;
            float2 xv = make_float2(0.f, 0.f);
            if (gr < n)
                xv = *(const float2*)(in + (size_t)gr * 128 + p * 2);
            if (MODE == 1) {
                xv.x = fmaxf(xv.x, 0.f);
                xv.y = fmaxf(xv.y, 0.f);
            }
            float h0f = __bfloat162float(__float2bfloat16_rn(xv.x));
            float h1f = __bfloat162float(__float2bfloat16_rn(xv.y));
            uint32_t off = aswz(row, p >> 2) + (p & 3) * 4;
            *(uint32_t*)(sm + SM_A_HI + off) = pkbf(xv.x, xv.y);
            *(uint32_t*)(sm + SM_A_LO + off) = pkbf(xv.x - h0f, xv.y - h1f);
        }
    }
    __syncthreads();

    // ---- compute: warp grid 4(m) x 4(n); warp tile 32 x 64 ----------------
    const int wm = wid >> 2;          // 0..3 -> m base
    const int wn = wid & 3;           // 0..3 -> n base
    const int mbase = wm * 32;
    const int nbase = wn * 64;

    float d[2][8][4];
#pragma unroll
    for (int mb = 0; mb < 2; mb++)
#pragma unroll
        for (int nb = 0; nb < 8; nb++)
#pragma unroll
            for (int q = 0; q < 4; q++) d[mb][nb][q] = 0.f;

    // per-thread ldmatrix address components
    const int aRow = lane & 15;       // row within m16 tile
    const int aKs  = lane >> 4;       // 0/1 -> k8 block select
    const int bTile = lane >> 3;      // 0..3
    const int bRow  = lane & 7;

#pragma unroll
    for (int s = 0; s < 3; s++) {
        const uint32_t aB = sbase + ((s == 2) ? SM_A_LO : SM_A_HI);
        const uint32_t bB = sbase + ((s == 1) ? SM_B_LO : SM_B_HI);
#pragma unroll
        for (int kk = 0; kk < 8; kk++) {
            const int kblk0 = kk * 2;
            uint32_t a[2][4];
#pragma unroll
            for (int mb = 0; mb < 2; mb++) {
                uint32_t row = mbase + mb * 16 + aRow;
                uint32_t addr = aB + aswz(row, kblk0 + aKs);
                ldsm_x4(a[mb][0], a[mb][1], a[mb][2], a[mb][3], addr);
            }
#pragma unroll
            for (int nb2 = 0; nb2 < 4; nb2++) {
                uint32_t row = nbase + nb2 * 16 + bRow + ((bTile >> 1) << 3);
                uint32_t addr = bB + aswz(row, kblk0 + (bTile & 1));
                uint32_t b0, b1, b2, b3;
                ldsm_x4(b0, b1, b2, b3, addr);
                uint32_t blo[2] = {b0, b1};
                uint32_t bhi[2] = {b2, b3};
                mma16816(d[0][nb2 * 2 + 0], a[0], blo);
                mma16816(d[1][nb2 * 2 + 0], a[1], blo);
                mma16816(d[0][nb2 * 2 + 1], a[0], bhi);
                mma16816(d[1][nb2 * 2 + 1], a[1], bhi);
            }
        }
    }

    // ---- epilogue: +bias, h0 (cols 0..127) -> agg, h1 (128..255) -> h1v ---
    const int colq = 2 * (lane & 3);
#pragma unroll
    for (int mb = 0; mb < 2; mb++) {
#pragma unroll
        for (int h = 0; h < 2; h++) {
            int row = m0 + mbase + mb * 16 + (lane >> 2) + h * 8;
            if (row >= n) continue;
#pragma unroll
            for (int nb = 0; nb < 8; nb++) {
                int col = nbase + nb * 8 + colq;
                float2 bv = *(const float2*)(bias256 + col);
                float2 v;
                v.x = d[mb][nb][2 * h + 0] + bv.x;
                v.y = d[mb][nb][2 * h + 1] + bv.y;
                if (col < 128)
                    *(float2*)(agg + (size_t)row * 128 + col) = v;
                else
                    *(float2*)(h1v + (size_t)row * 128 + (col - 128)) = v;
            }
        }
    }
}

// ======================= edge scatter (HBM-roofline) =======================
__global__ void scatter128_kernel(const int2* __restrict__ edges,
                                  const float* __restrict__ h1,
                                  float* __restrict__ agg, int E)
{
    int w = (int)((blockIdx.x * (unsigned)blockDim.x + threadIdx.x) >> 5);
    int lane = threadIdx.x & 31;
    if (w >= E) return;
    int2 e = __ldg(&edges[w]);
    const float* hs = h1 + (size_t)e.x * 128;
    const float* hd = h1 + (size_t)e.y * 128;
    float* as_ = agg + (size_t)e.x * 128;
    float* ad_ = agg + (size_t)e.y * 128;
#pragma unroll
    for (int f = 0; f < 4; f++) {
        int o = f * 32 + lane;
        atomicAdd(as_ + o, hd[o]);
    }
#pragma unroll
    for (int f = 0; f < 4; f++) {
        int o = f * 32 + lane;
        atomicAdd(ad_ + o, hs[o]);
    }
}

// ======================= final layer (dout=3) ==============================
__global__ __launch_bounds__(256)
void final_kernel(const float* __restrict__ in, const float* __restrict__ feat,
                  const float* __restrict__ W0, const float* __restrict__ b0,
                  const float* __restrict__ W1, const float* __restrict__ b1,
                  float* __restrict__ out, float* __restrict__ h1s, int n)
{
    __shared__ float ws[128][6];
    __shared__ float bs[6];
    int tid = threadIdx.x;
    for (int idx = tid; idx < 768; idx += 256) {
        int k = idx / 6, j = idx % 6;
        ws[k][j] = (j < 3) ? __ldg(&W0[k * 3 + j]) : __ldg(&W1[k * 3 + (j - 3)]);
    }
    if (tid < 3)      bs[tid] = __ldg(&b0[tid]);
    else if (tid < 6) bs[tid] = __ldg(&b1[tid - 3]);
    __syncthreads();

    int lane = tid & 31;
    int node = blockIdx.x * 8 + (tid >> 5);
    if (node >= n) return;

    float acc[6] = {0.f, 0.f, 0.f, 0.f, 0.f, 0.f};
    const float* xin = in   + (size_t)node * 128;
    const float* xf  = feat + (size_t)node * 128;
#pragma unroll
    for (int f = 0; f < 4; f++) {
        int k = f * 32 + lane;
        float x = fmaxf(xin[k], 0.f) + xf[k];
#pragma unroll
        for (int j = 0; j < 6; j++) acc[j] += x * ws[k][j];
    }
#pragma unroll
    for (int j = 0; j < 6; j++) {
#pragma unroll
        for (int o = 16; o > 0; o >>= 1)
            acc[j] += __shfl_xor_sync(0xffffffffu, acc[j], o);
    }
    if (lane == 0) {
        out[node * 3 + 0] = acc[0] + bs[0];
        out[node * 3 + 1] = acc[1] + bs[1];
        out[node * 3 + 2] = acc[2] + bs[2];
        h1s[node * 3 + 0] = acc[3] + bs[3];
        h1s[node * 3 + 1] = acc[4] + bs[4];
        h1s[node * 3 + 2] = acc[5] + bs[5];
    }
}

__global__ void scatter3_kernel(const int2* __restrict__ edges,
                                const float* __restrict__ h1s,
                                float* __restrict__ out, int E)
{
    int t = blockIdx.x * blockDim.x + threadIdx.x;
    if (t >= E) return;
    int2 e = __ldg(&edges[t]);
    size_t s = (size_t)e.x * 3, d = (size_t)e.y * 3;
    float hs0 = h1s[s + 0], hs1 = h1s[s + 1], hs2 = h1s[s + 2];
    float hd0 = h1s[d + 0], hd1 = h1s[d + 1], hd2 = h1s[d + 2];
    atomicAdd(out + s + 0, hd0);
    atomicAdd(out + s + 1, hd1);
    atomicAdd(out + s + 2, hd2);
    atomicAdd(out + d + 0, hs0);
    atomicAdd(out + d + 1, hs1);
    atomicAdd(out + d + 2, hs2);
}

// ======================= launch ============================================
extern "C" void kernel_launch(void* const* d_in, const int* in_sizes, int n_in,
                              void* d_out, int out_size)
{
    const float* feat  = (const float*)d_in[0];
    const int2*  edges = (const int2*) d_in[1];
    const int N = in_sizes[0] / 128;
    const int E = in_sizes[1] / 2;

    const float *W0[4], *B0[4], *W1[4], *B1[4];
    for (int i = 0; i < 4; i++) {
        W0[i] = (const float*)d_in[2 + 4 * i];
        B0[i] = (const float*)d_in[3 + 4 * i];
        W1[i] = (const float*)d_in[4 + 4 * i];
        B1[i] = (const float*)d_in[5 + 4 * i];
    }

    float *bufA, *bufB, *h1, *h1s, *biasAll;
    __nv_bfloat16 *whiAll, *wloAll;
    cudaGetSymbolAddress((void**)&bufA, g_bufA);
    cudaGetSymbolAddress((void**)&bufB, g_bufB);
    cudaGetSymbolAddress((void**)&h1,   g_h1);
    cudaGetSymbolAddress((void**)&h1s,  g_h1s);
    cudaGetSymbolAddress((void**)&whiAll, g_Whi);
    cudaGetSymbolAddress((void**)&wloAll, g_Wlo);
    cudaGetSymbolAddress((void**)&biasAll, g_bias);

    cudaFuncSetAttribute(gemm_mma_kernel<0>, cudaFuncAttributeMaxDynamicSharedMemorySize, SM_DYN);
    cudaFuncSetAttribute(gemm_mma_kernel<1>, cudaFuncAttributeMaxDynamicSharedMemorySize, SM_DYN);

    for (int l = 0; l < 3; l++) {
        prep_w_kernel<<<16, 256>>>(W0[l], B0[l], W1[l], B1[l],
                                   whiAll + l * 256 * 128, wloAll + l * 256 * 128,
                                   biasAll + l * 256);
    }

    const int gBlocks = (N + 127) / 128;
    const int sBlocks = (E + 7) / 8;
    float* out = (float*)d_out;

    gemm_mma_kernel<0><<<gBlocks, 512, SM_DYN>>>(feat, whiAll, wloAll, biasAll, bufA, h1, N);
    scatter128_kernel<<<sBlocks, 256>>>(edges, h1, bufA, E);

    gemm_mma_kernel<1><<<gBlocks, 512, SM_DYN>>>(bufA, whiAll + 256 * 128, wloAll + 256 * 128,
                                                 biasAll + 256, bufB, h1, N);
    scatter128_kernel<<<sBlocks, 256>>>(edges, h1, bufB, E);

    gemm_mma_kernel<1><<<gBlocks, 512, SM_DYN>>>(bufB, whiAll + 2 * 256 * 128, wloAll + 2 * 256 * 128,
                                                 biasAll + 2 * 256, bufA, h1, N);
    scatter128_kernel<<<sBlocks, 256>>>(edges, h1, bufA, E);

    final_kernel<<<(N + 7) / 8, 256>>>(bufA, feat, W0[3], B0[3], W1[3], B1[3], out, h1s, N);
    scatter3_kernel<<<(E + 255) / 256, 256>>>(edges, h1s, out, E);
}

// round 4
// speedup vs baseline: 1.4638x; 1.4638x over previous
#include <cuda_runtime.h>
#include <cuda_bf16.h>
#include <cstdint>

// ---------------------------------------------------------------------------
// MeshRefineNet on GB300 (sm_103a), R4:
//   * persistent HMMA split-bf16 dual-GEMM (B staged once per CTA, A pipelined)
//   * CSR build + warp-per-node gather (replaces atomic scatter)
// layer i: h0 = x@W0+b0; h1 = x@W1+b1; out = h0 + sum_{j in N(i)} h1[j]
// relu after layers 0..2; skip (x += features) before layer 3; layer 3 dout=3.
// ---------------------------------------------------------------------------

#define NMAX 320000
#define EMAX 1000000

__device__ float g_bufA[NMAX * 128];
__device__ float g_bufB[NMAX * 128];
__device__ float g_h1 [NMAX * 128];
__device__ float g_h1s[NMAX * 3];

// pre-split weight images, linear Bt[n][k] row-major (built once per launch)
__device__ __align__(16) __nv_bfloat16 g_Whi[3][256 * 128];
__device__ __align__(16) __nv_bfloat16 g_Wlo[3][256 * 128];
__device__ float g_bias[3][256];

// CSR scratch
__device__ int g_deg[NMAX];
__device__ int g_cur[NMAX];
__device__ int g_rowstart[NMAX + 1];
__device__ int g_adj[2 * EMAX];
__device__ int g_bsum[512];

// ======================= helpers ===========================================
__device__ __forceinline__ uint32_t smem_to_u32(const void* p) {
    uint32_t a;
    asm("{ .reg .u64 t; cvta.to.shared.u64 t, %1; cvt.u32.u64 %0, t; }"
        : "=r"(a) : "l"(p));
    return a;
}
__device__ __forceinline__ uint32_t pkbf(float a, float b) {
    __nv_bfloat162 t = __floats2bfloat162_rn(a, b);
    return *(uint32_t*)&t;
}
// XOR-swizzled offset for bf16 tile images with 256B rows (128 halves/row).
__device__ __forceinline__ uint32_t aswz(uint32_t row, uint32_t kblk) {
    return row * 256u + ((((kblk ^ row) & 7u) | (kblk & 8u)) << 4);
}
__device__ __forceinline__ void ldsm_x4(uint32_t& r0, uint32_t& r1,
                                        uint32_t& r2, uint32_t& r3, uint32_t addr) {
    asm volatile("ldmatrix.sync.aligned.m8n8.x4.shared.b16 {%0,%1,%2,%3}, [%4];"
                 : "=r"(r0), "=r"(r1), "=r"(r2), "=r"(r3) : "r"(addr));
}
__device__ __forceinline__ void mma16816(float* d, const uint32_t* a,
                                         const uint32_t* b) {
    asm volatile("mma.sync.aligned.m16n8k16.row.col.f32.bf16.bf16.f32 "
                 "{%0,%1,%2,%3}, {%4,%5,%6,%7}, {%8,%9}, {%0,%1,%2,%3};"
                 : "+f"(d[0]), "+f"(d[1]), "+f"(d[2]), "+f"(d[3])
                 : "r"(a[0]), "r"(a[1]), "r"(a[2]), "r"(a[3]),
                   "r"(b[0]), "r"(b[1]));
}

// ======================= weight prep (once per launch) =====================
__global__ void prep_w_kernel(const float* __restrict__ W0, const float* __restrict__ b0,
                              const float* __restrict__ W1, const float* __restrict__ b1,
                              __nv_bfloat16* __restrict__ hi, __nv_bfloat16* __restrict__ lo,
                              float* __restrict__ biasOut)
{
    int t0 = blockIdx.x * blockDim.x + threadIdx.x;
    if (t0 < 256) biasOut[t0] = (t0 < 128) ? b0[t0] : b1[t0 - 128];
    uint32_t* hip = (uint32_t*)hi;
    uint32_t* lop = (uint32_t*)lo;
    for (int idx = t0; idx < 256 * 64; idx += blockDim.x * gridDim.x) {
        int n = idx >> 6, p = idx & 63;
        int k = p * 2;
        float x0, x1;
        if (n < 128) { x0 = W0[k * 128 + n]; x1 = W0[(k + 1) * 128 + n]; }
        else         { x0 = W1[k * 128 + n - 128]; x1 = W1[(k + 1) * 128 + n - 128]; }
        float h0f = __bfloat162float(__float2bfloat16_rn(x0));
        float h1f = __bfloat162float(__float2bfloat16_rn(x1));
        hip[idx] = pkbf(x0, x1);
        lop[idx] = pkbf(x0 - h0f, x1 - h1f);
    }
}

// ======================= CSR build =========================================
__global__ void zero_deg_kernel(int* deg, int n) {
    int i = blockIdx.x * blockDim.x + threadIdx.x;
    if (i < n) deg[i] = 0;
}
__global__ void count_deg_kernel(const int2* __restrict__ edges, int* deg, int E) {
    int e = blockIdx.x * blockDim.x + threadIdx.x;
    if (e >= E) return;
    int2 ed = __ldg(&edges[e]);
    atomicAdd(&deg[ed.x], 1);
    atomicAdd(&deg[ed.y], 1);
}
// phase A: per-block (1024 elems) local exclusive scan + block sums
__global__ __launch_bounds__(1024)
void scanA_kernel(const int* __restrict__ deg, int* rowstart, int* bsum, int n) {
    __shared__ int s[1024];
    int t = threadIdx.x;
    int i = blockIdx.x * 1024 + t;
    int v = (i < n) ? deg[i] : 0;
    s[t] = v;
    __syncthreads();
#pragma unroll
    for (int o = 1; o < 1024; o <<= 1) {
        int x = (t >= o) ? s[t - o] : 0;
        __syncthreads();
        s[t] += x;
        __syncthreads();
    }
    if (i < n) rowstart[i] = s[t] - v;     // local exclusive
    if (t == 1023) bsum[blockIdx.x] = s[1023];
}
// phase B: exclusive scan of block sums (NB <= 512)
__global__ __launch_bounds__(512)
void scanB_kernel(int* bsum, int nb) {
    __shared__ int s[512];
    int t = threadIdx.x;
    int v = (t < nb) ? bsum[t] : 0;
    s[t] = v;
    __syncthreads();
#pragma unroll
    for (int o = 1; o < 512; o <<= 1) {
        int x = (t >= o) ? s[t - o] : 0;
        __syncthreads();
        s[t] += x;
        __syncthreads();
    }
    if (t < nb) bsum[t] = s[t] - v;        // exclusive
}
// phase C: add block offsets, init cursor, set sentinel
__global__ __launch_bounds__(1024)
void scanC_kernel(int* rowstart, int* cur, const int* __restrict__ bsum,
                  int n, int total) {
    int i = blockIdx.x * 1024 + threadIdx.x;
    if (i < n) {
        int r = rowstart[i] + bsum[blockIdx.x];
        rowstart[i] = r;
        cur[i] = r;
    }
    if (i == 0) rowstart[n] = total;
}
__global__ void fill_adj_kernel(const int2* __restrict__ edges, int* cur,
                                int* adj, int E) {
    int e = blockIdx.x * blockDim.x + threadIdx.x;
    if (e >= E) return;
    int2 ed = __ldg(&edges[e]);
    int ps = atomicAdd(&cur[ed.x], 1);
    adj[ps] = ed.y;
    int pd = atomicAdd(&cur[ed.y], 1);
    adj[pd] = ed.x;
}

// ======================= persistent HMMA dual-GEMM =========================
// smem: B_hi(64K) | B_lo(64K) | A dbuf 2 x (hi 16K + lo 16K) = 192KB
static constexpr int SM_B_HI = 0;
static constexpr int SM_B_LO = 65536;
static constexpr int SM_A    = 131072;      // + buf*32768; lo at +16384
static constexpr int SM_DYN  = 196608;

template<int MODE>   // 0 = raw input, 1 = relu(input)
__global__ __launch_bounds__(512, 1)
void gemm_persist_kernel(const float* __restrict__ in,
                         const __nv_bfloat16* __restrict__ Whi,
                         const __nv_bfloat16* __restrict__ Wlo,
                         const float* __restrict__ bias256,
                         float* __restrict__ agg, float* __restrict__ h1v,
                         int n, int numTiles)
{
    extern __shared__ char sm[];
    const uint32_t sbase = smem_to_u32(sm);
    const int tid  = threadIdx.x;
    const int wid  = tid >> 5;
    const int lane = tid & 31;

    // ---- stage B hi/lo once (swizzled) ----
    {
        const uint32_t* srcH = (const uint32_t*)Whi;
        const uint32_t* srcL = (const uint32_t*)Wlo;
#pragma unroll
        for (int u = 0; u < 32; u++) {
            int idx = u * 512 + tid;
            int row = idx >> 6, p = idx & 63;
            uint32_t off = aswz(row, p >> 2) + (p & 3) * 4;
            *(uint32_t*)(sm + SM_B_HI + off) = srcH[idx];
            *(uint32_t*)(sm + SM_B_LO + off) = srcL[idx];
        }
    }

    int tile = blockIdx.x;
    if (tile >= numTiles) { __syncthreads(); return; }

    // ---- stage A tile0 into buf0 ----
    {
        int tb = tile * 64;
#pragma unroll
        for (int u = 0; u < 8; u++) {
            int idx = u * 512 + tid;
            int row = idx >> 6, p = idx & 63;
            int gr = tb + row;
            float2 xv = make_float2(0.f, 0.f);
            if (gr < n) xv = *(const float2*)(in + (size_t)gr * 128 + p * 2);
            if (MODE == 1) { xv.x = fmaxf(xv.x, 0.f); xv.y = fmaxf(xv.y, 0.f); }
            float hx = __bfloat162float(__float2bfloat16_rn(xv.x));
            float hy = __bfloat162float(__float2bfloat16_rn(xv.y));
            uint32_t off = aswz(row, p >> 2) + (p & 3) * 4;
            *(uint32_t*)(sm + SM_A + off)         = pkbf(xv.x, xv.y);
            *(uint32_t*)(sm + SM_A + 16384 + off) = pkbf(xv.x - hx, xv.y - hy);
        }
    }
    __syncthreads();

    // warp grid: 2(m) x 8(n); warp tile 32x32
    const int mbase = (wid & 1) * 32;
    const int nbase = (wid >> 1) * 32;
    const int aRow  = lane & 15;
    const int aKs   = lane >> 4;
    const int bTile = lane >> 3;
    const int bRow  = (lane & 7) + ((bTile >> 1) << 3);
    const int colq  = 2 * (lane & 3);

    for (int it = 0; ; it++) {
        const int buf = it & 1;
        const int tb = tile * 64;
        const int next = tile + gridDim.x;
        const bool hasNext = next < numTiles;

        // prefetch next A tile (LDG under compute)
        float2 pf[8];
        if (hasNext) {
            int ntb = next * 64;
#pragma unroll
            for (int u = 0; u < 8; u++) {
                int idx = u * 512 + tid;
                int row = idx >> 6, p = idx & 63;
                int gr = ntb + row;
                pf[u] = (gr < n) ? *(const float2*)(in + (size_t)gr * 128 + p * 2)
                                 : make_float2(0.f, 0.f);
            }
        }

        // ---- compute ----
        float d[2][4][4];
#pragma unroll
        for (int mb = 0; mb < 2; mb++)
#pragma unroll
            for (int nb = 0; nb < 4; nb++)
#pragma unroll
                for (int q = 0; q < 4; q++) d[mb][nb][q] = 0.f;

        const uint32_t abuf = sbase + SM_A + buf * 32768;
#pragma unroll
        for (int s = 0; s < 3; s++) {
            const uint32_t aB = abuf + ((s == 2) ? 16384 : 0);
            const uint32_t bB = sbase + ((s == 1) ? SM_B_LO : SM_B_HI);
#pragma unroll
            for (int kk = 0; kk < 8; kk++) {
                const int kblk0 = kk * 2;
                uint32_t a[2][4];
#pragma unroll
                for (int mb = 0; mb < 2; mb++) {
                    uint32_t addr = aB + aswz(mbase + mb * 16 + aRow, kblk0 + aKs);
                    ldsm_x4(a[mb][0], a[mb][1], a[mb][2], a[mb][3], addr);
                }
#pragma unroll
                for (int nb2 = 0; nb2 < 2; nb2++) {
                    uint32_t addr = bB + aswz(nbase + nb2 * 16 + bRow,
                                              kblk0 + (bTile & 1));
                    uint32_t b0, b1, b2, b3;
                    ldsm_x4(b0, b1, b2, b3, addr);
                    uint32_t blo[2] = {b0, b1};
                    uint32_t bhi[2] = {b2, b3};
                    mma16816(d[0][nb2 * 2 + 0], a[0], blo);
                    mma16816(d[1][nb2 * 2 + 0], a[1], blo);
                    mma16816(d[0][nb2 * 2 + 1], a[0], bhi);
                    mma16816(d[1][nb2 * 2 + 1], a[1], bhi);
                }
            }
        }

        // ---- epilogue: +bias, cols<128 -> agg(h0), else h1 ----
#pragma unroll
        for (int mb = 0; mb < 2; mb++) {
#pragma unroll
            for (int h = 0; h < 2; h++) {
                int row = tb + mbase + mb * 16 + (lane >> 2) + h * 8;
                if (row >= n) continue;
#pragma unroll
                for (int nb = 0; nb < 4; nb++) {
                    int col = nbase + nb * 8 + colq;
                    float2 bv = __ldg((const float2*)(bias256 + col));
                    float2 v;
                    v.x = d[mb][nb][2 * h + 0] + bv.x;
                    v.y = d[mb][nb][2 * h + 1] + bv.y;
                    if (col < 128)
                        *(float2*)(agg + (size_t)row * 128 + col) = v;
                    else
                        *(float2*)(h1v + (size_t)row * 128 + (col - 128)) = v;
                }
            }
        }

        if (!hasNext) break;

        // ---- convert + store prefetched tile into other buffer ----
        {
            const uint32_t nbuf = sbase + SM_A + (buf ^ 1) * 32768;
#pragma unroll
            for (int u = 0; u < 8; u++) {
                int idx = u * 512 + tid;
                int row = idx >> 6, p = idx & 63;
                float2 xv = pf[u];
                if (MODE == 1) { xv.x = fmaxf(xv.x, 0.f); xv.y = fmaxf(xv.y, 0.f); }
                float hx = __bfloat162float(__float2bfloat16_rn(xv.x));
                float hy = __bfloat162float(__float2bfloat16_rn(xv.y));
                uint32_t off = aswz(row, p >> 2) + (p & 3) * 4;
                *(uint32_t*)(nbuf - sbase + sm + off)         = pkbf(xv.x, xv.y);
                *(uint32_t*)(nbuf - sbase + sm + 16384 + off) = pkbf(xv.x - hx, xv.y - hy);
            }
        }
        tile = next;
        __syncthreads();
    }
}

// ======================= CSR gather (128-wide) =============================
__global__ __launch_bounds__(256)
void gather128_kernel(const int* __restrict__ rowstart, const int* __restrict__ adj,
                      const float* __restrict__ h1, float* __restrict__ agg, int n)
{
    int node = blockIdx.x * 8 + (threadIdx.x >> 5);
    int lane = threadIdx.x & 31;
    if (node >= n) return;
    int rs = __ldg(&rowstart[node]);
    int re = __ldg(&rowstart[node + 1]);
    float* ap = agg + (size_t)node * 128 + lane * 4;
    float4 acc = *(float4*)ap;
    int e = rs;
    for (; e + 1 < re; e += 2) {
        int j0 = __ldg(&adj[e]);
        int j1 = __ldg(&adj[e + 1]);
        float4 v0 = __ldg((const float4*)(h1 + (size_t)j0 * 128 + lane * 4));
        float4 v1 = __ldg((const float4*)(h1 + (size_t)j1 * 128 + lane * 4));
        acc.x += v0.x + v1.x; acc.y += v0.y + v1.y;
        acc.z += v0.z + v1.z; acc.w += v0.w + v1.w;
    }
    if (e < re) {
        int j = __ldg(&adj[e]);
        float4 v = __ldg((const float4*)(h1 + (size_t)j * 128 + lane * 4));
        acc.x += v.x; acc.y += v.y; acc.z += v.z; acc.w += v.w;
    }
    *(float4*)ap = acc;
}

// ======================= final layer (dout=3) ==============================
__global__ __launch_bounds__(256)
void final_kernel(const float* __restrict__ in, const float* __restrict__ feat,
                  const float* __restrict__ W0, const float* __restrict__ b0,
                  const float* __restrict__ W1, const float* __restrict__ b1,
                  float* __restrict__ out, float* __restrict__ h1s, int n)
{
    __shared__ float ws[128][6];
    __shared__ float bs[6];
    int tid = threadIdx.x;
    for (int idx = tid; idx < 768; idx += 256) {
        int k = idx / 6, j = idx % 6;
        ws[k][j] = (j < 3) ? __ldg(&W0[k * 3 + j]) : __ldg(&W1[k * 3 + (j - 3)]);
    }
    if (tid < 3)      bs[tid] = __ldg(&b0[tid]);
    else if (tid < 6) bs[tid] = __ldg(&b1[tid - 3]);
    __syncthreads();

    int lane = tid & 31;
    int node = blockIdx.x * 8 + (tid >> 5);
    if (node >= n) return;

    float acc[6] = {0.f, 0.f, 0.f, 0.f, 0.f, 0.f};
    const float* xin = in   + (size_t)node * 128;
    const float* xf  = feat + (size_t)node * 128;
#pragma unroll
    for (int f = 0; f < 4; f++) {
        int k = f * 32 + lane;
        float x = fmaxf(xin[k], 0.f) + xf[k];
#pragma unroll
        for (int j = 0; j < 6; j++) acc[j] += x * ws[k][j];
    }
#pragma unroll
    for (int j = 0; j < 6; j++) {
#pragma unroll
        for (int o = 16; o > 0; o >>= 1)
            acc[j] += __shfl_xor_sync(0xffffffffu, acc[j], o);
    }
    if (lane == 0) {
        out[node * 3 + 0] = acc[0] + bs[0];
        out[node * 3 + 1] = acc[1] + bs[1];
        out[node * 3 + 2] = acc[2] + bs[2];
        h1s[node * 3 + 0] = acc[3] + bs[3];
        h1s[node * 3 + 1] = acc[4] + bs[4];
        h1s[node * 3 + 2] = acc[5] + bs[5];
    }
}

// final gather (3-wide): thread per node
__global__ void gather3_kernel(const int* __restrict__ rowstart,
                               const int* __restrict__ adj,
                               const float* __restrict__ h1s,
                               float* __restrict__ out, int n)
{
    int i = blockIdx.x * blockDim.x + threadIdx.x;
    if (i >= n) return;
    int rs = __ldg(&rowstart[i]);
    int re = __ldg(&rowstart[i + 1]);
    float a0 = 0.f, a1 = 0.f, a2 = 0.f;
    for (int e = rs; e < re; e++) {
        int j = __ldg(&adj[e]);
        a0 += __ldg(&h1s[j * 3 + 0]);
        a1 += __ldg(&h1s[j * 3 + 1]);
        a2 += __ldg(&h1s[j * 3 + 2]);
    }
    out[i * 3 + 0] += a0;
    out[i * 3 + 1] += a1;
    out[i * 3 + 2] += a2;
}

// ======================= launch ============================================
extern "C" void kernel_launch(void* const* d_in, const int* in_sizes, int n_in,
                              void* d_out, int out_size)
{
    const float* feat  = (const float*)d_in[0];
    const int2*  edges = (const int2*) d_in[1];
    const int N = in_sizes[0] / 128;
    const int E = in_sizes[1] / 2;

    const float *W0[4], *B0[4], *W1[4], *B1[4];
    for (int i = 0; i < 4; i++) {
        W0[i] = (const float*)d_in[2 + 4 * i];
        B0[i] = (const float*)d_in[3 + 4 * i];
        W1[i] = (const float*)d_in[4 + 4 * i];
        B1[i] = (const float*)d_in[5 + 4 * i];
    }

    float *bufA, *bufB, *h1, *h1s, *biasAll;
    __nv_bfloat16 *whiAll, *wloAll;
    int *deg, *cur, *rowstart, *adj, *bsum;
    cudaGetSymbolAddress((void**)&bufA, g_bufA);
    cudaGetSymbolAddress((void**)&bufB, g_bufB);
    cudaGetSymbolAddress((void**)&h1,   g_h1);
    cudaGetSymbolAddress((void**)&h1s,  g_h1s);
    cudaGetSymbolAddress((void**)&whiAll, g_Whi);
    cudaGetSymbolAddress((void**)&wloAll, g_Wlo);
    cudaGetSymbolAddress((void**)&biasAll, g_bias);
    cudaGetSymbolAddress((void**)&deg, g_deg);
    cudaGetSymbolAddress((void**)&cur, g_cur);
    cudaGetSymbolAddress((void**)&rowstart, g_rowstart);
    cudaGetSymbolAddress((void**)&adj, g_adj);
    cudaGetSymbolAddress((void**)&bsum, g_bsum);

    cudaFuncSetAttribute(gemm_persist_kernel<0>, cudaFuncAttributeMaxDynamicSharedMemorySize, SM_DYN);
    cudaFuncSetAttribute(gemm_persist_kernel<1>, cudaFuncAttributeMaxDynamicSharedMemorySize, SM_DYN);

    // weight prep
    for (int l = 0; l < 3; l++) {
        prep_w_kernel<<<16, 256>>>(W0[l], B0[l], W1[l], B1[l],
                                   whiAll + l * 256 * 128, wloAll + l * 256 * 128,
                                   biasAll + l * 256);
    }

    // CSR build
    const int NB = (N + 1023) / 1024;
    zero_deg_kernel<<<(N + 255) / 256, 256>>>(deg, N);
    count_deg_kernel<<<(E + 255) / 256, 256>>>(edges, deg, E);
    scanA_kernel<<<NB, 1024>>>(deg, rowstart, bsum, N);
    scanB_kernel<<<1, 512>>>(bsum, NB);
    scanC_kernel<<<NB, 1024>>>(rowstart, cur, bsum, N, 2 * E);
    fill_adj_kernel<<<(E + 255) / 256, 256>>>(edges, cur, adj, E);

    const int numTiles = (N + 63) / 64;
    const int PGRID = 148;
    const int gaBlocks = (N + 7) / 8;
    float* out = (float*)d_out;

    gemm_persist_kernel<0><<<PGRID, 512, SM_DYN>>>(feat, whiAll, wloAll, biasAll,
                                                   bufA, h1, N, numTiles);
    gather128_kernel<<<gaBlocks, 256>>>(rowstart, adj, h1, bufA, N);

    gemm_persist_kernel<1><<<PGRID, 512, SM_DYN>>>(bufA, whiAll + 256 * 128, wloAll + 256 * 128,
                                                   biasAll + 256, bufB, h1, N, numTiles);
    gather128_kernel<<<gaBlocks, 256>>>(rowstart, adj, h1, bufB, N);

    gemm_persist_kernel<1><<<PGRID, 512, SM_DYN>>>(bufB, whiAll + 2 * 256 * 128, wloAll + 2 * 256 * 128,
                                                   biasAll + 2 * 256, bufA, h1, N, numTiles);
    gather128_kernel<<<gaBlocks, 256>>>(rowstart, adj, h1, bufA, N);

    final_kernel<<<(N + 7) / 8, 256>>>(bufA, feat, W0[3], B0[3], W1[3], B1[3], out, h1s, N);
    gather3_kernel<<<(N + 255) / 256, 256>>>(rowstart, adj, h1s, out, N);
}